// round 4
// baseline (speedup 1.0000x reference)
#include <cuda_runtime.h>

#define NPTS  4096
#define NCTA  128
#define TPB   256
#define IPC   32          // i-points per CTA
#define STEPS 10

// shared memory layout (bytes)
#define SM_SJ    0                       // float4[4096]  = 65536
#define SM_KEY   (NPTS*16)               // u64[32][32]   = 8192
#define SM_MYPC  (SM_KEY + 32*32*8)      // float[96]
#define SM_MYP1  (SM_MYPC + 96*4)        // float[96]
#define SM_SRT   (SM_MYP1 + 96*4)        // float[12] (+pad)
#define SM_SRED  (SM_SRT + 16*4)         // float[4][15]
#define SM_TOTAL (SM_SRED + 4*15*4 + 64)

// global scratch (no allocations allowed)
__device__ float g_part[NCTA][16];
__device__ int   g_sync[64];   // [0..STEPS] arrival counters

__device__ __forceinline__ unsigned int fkey(float f) {
    unsigned int u = __float_as_uint(f);
    return (u & 0x80000000u) ? ~u : (u | 0x80000000u);
}

// ---------------------------------------------------------------------------
// Fast float Kabsch from raw product sums P[r*3+c]=sum s_r d_c.
// H = P - n c1 c2^T ; R = V diag(1,1,det) U^T ; t = c2 - R c1.
// Fixed 5 Jacobi sweeps, fully unrolled, MUFU-based div/rsqrt.
// ---------------------------------------------------------------------------
__device__ __forceinline__ void kabsch3(const float* __restrict__ P, float n,
                                        const float c1[3], const float c2[3],
                                        float R[9], float t[3])
{
    float H[9];
    #pragma unroll
    for (int r = 0; r < 3; r++)
        #pragma unroll
        for (int c = 0; c < 3; c++)
            H[r*3+c] = P[r*3+c] - n*c1[r]*c2[c];

    float S[3][3], V[3][3];
    #pragma unroll
    for (int r = 0; r < 3; r++)
        #pragma unroll
        for (int c = 0; c < 3; c++) {
            S[r][c] = H[0+r]*H[0+c] + H[3+r]*H[3+c] + H[6+r]*H[6+c];
            V[r][c] = (r == c) ? 1.f : 0.f;
        }

    #pragma unroll
    for (int sweep = 0; sweep < 5; sweep++) {
        #pragma unroll
        for (int pair = 0; pair < 3; pair++) {
            const int p = (pair == 2) ? 1 : 0;
            const int q = (pair == 0) ? 1 : 2;
            float apq = S[p][q];
            if (fabsf(apq) > 1e-30f) {
                float theta = __fdividef(S[q][q] - S[p][p], 2.f*apq);
                float tj = __fdividef((theta >= 0.f) ? 1.f : -1.f,
                                      fabsf(theta) + sqrtf(fmaf(theta,theta,1.f)));
                float cj = rsqrtf(fmaf(tj,tj,1.f));
                float sj = tj*cj;
                #pragma unroll
                for (int k = 0; k < 3; k++) {
                    float skp = S[k][p], skq = S[k][q];
                    S[k][p] = cj*skp - sj*skq;
                    S[k][q] = sj*skp + cj*skq;
                }
                #pragma unroll
                for (int k = 0; k < 3; k++) {
                    float spk = S[p][k], sqk = S[q][k];
                    S[p][k] = cj*spk - sj*sqk;
                    S[q][k] = sj*spk + cj*sqk;
                }
                #pragma unroll
                for (int k = 0; k < 3; k++) {
                    float vkp = V[k][p], vkq = V[k][q];
                    V[k][p] = cj*vkp - sj*vkq;
                    V[k][q] = sj*vkp + cj*vkq;
                }
            }
        }
    }

    float lam[3] = { S[0][0], S[1][1], S[2][2] };
    int ord[3] = {0,1,2};
    #pragma unroll
    for (int a = 0; a < 2; a++)
        #pragma unroll
        for (int b = a+1; b < 3; b++)
            if (lam[ord[b]] > lam[ord[a]]) { int tmp = ord[a]; ord[a] = ord[b]; ord[b] = tmp; }
    float Vs[3][3];
    #pragma unroll
    for (int c = 0; c < 3; c++)
        #pragma unroll
        for (int r = 0; r < 3; r++) Vs[r][c] = V[r][ord[c]];

    float U[3][3];
    #pragma unroll
    for (int c = 0; c < 3; c++) {
        float u0 = H[0]*Vs[0][c] + H[1]*Vs[1][c] + H[2]*Vs[2][c];
        float u1 = H[3]*Vs[0][c] + H[4]*Vs[1][c] + H[5]*Vs[2][c];
        float u2 = H[6]*Vs[0][c] + H[7]*Vs[1][c] + H[8]*Vs[2][c];
        float n2 = fmaf(u0,u0, fmaf(u1,u1, u2*u2));
        if (n2 > 1e-30f) {
            float inv = rsqrtf(n2);
            u0 *= inv; u1 *= inv; u2 *= inv;
        } else if (c == 2) {   // rank-deficient fallback: u2 = u0 x u1
            u0 = U[1][0]*U[2][1] - U[2][0]*U[1][1];
            u1 = U[2][0]*U[0][1] - U[0][0]*U[2][1];
            u2 = U[0][0]*U[1][1] - U[1][0]*U[0][1];
        }
        U[0][c] = u0; U[1][c] = u1; U[2][c] = u2;
    }
    float detV = Vs[0][0]*(Vs[1][1]*Vs[2][2]-Vs[1][2]*Vs[2][1])
               - Vs[0][1]*(Vs[1][0]*Vs[2][2]-Vs[1][2]*Vs[2][0])
               + Vs[0][2]*(Vs[1][0]*Vs[2][1]-Vs[1][1]*Vs[2][0]);
    float detU = U[0][0]*(U[1][1]*U[2][2]-U[1][2]*U[2][1])
               - U[0][1]*(U[1][0]*U[2][2]-U[1][2]*U[2][0])
               + U[0][2]*(U[1][0]*U[2][1]-U[1][1]*U[2][0]);
    float d = (detV*detU < 0.f) ? -1.f : 1.f;

    #pragma unroll
    for (int r = 0; r < 3; r++)
        #pragma unroll
        for (int c = 0; c < 3; c++)
            R[r*3+c] = Vs[r][0]*U[c][0] + Vs[r][1]*U[c][1] + d*Vs[r][2]*U[c][2];
    #pragma unroll
    for (int r = 0; r < 3; r++)
        t[r] = c2[r] - (R[r*3+0]*c1[0] + R[r*3+1]*c1[1] + R[r*3+2]*c1[2]);
}

// warp-reduce 15 accumulators (full warp, fixed order -> deterministic)
__device__ __forceinline__ void wred15(float a[15]) {
    #pragma unroll
    for (int q = 0; q < 15; q++)
        #pragma unroll
        for (int off = 16; off; off >>= 1)
            a[q] += __shfl_down_sync(0xffffffffu, a[q], off);
}

// ---------------------------------------------------------------------------
// Persistent kernel: all STEPS iterations + final Kabsch. grid=NCTA, block=TPB.
// Every CTA redundantly reduces the 128 partials and solves Kabsch locally
// (identical fp32 ops on identical data -> identical R,t in every CTA).
// ---------------------------------------------------------------------------
__global__ void __launch_bounds__(TPB, 1)
icp_all(const float* __restrict__ p1, const float* __restrict__ p2,
        float* __restrict__ out)
{
    extern __shared__ unsigned char smem[];
    float4*             sj   = (float4*)(smem + SM_SJ);
    unsigned long long* key  = (unsigned long long*)(smem + SM_KEY);
    float*              mypc = (float*)(smem + SM_MYPC);
    float*              myp1 = (float*)(smem + SM_MYP1);
    float*              srt  = (float*)(smem + SM_SRT);
    float*              sred = (float*)(smem + SM_SRED);

    const int cta = blockIdx.x;
    const int tid = threadIdx.x;

    // load p2 (+ precomputed 0.5|q|^2) into shared; reused all iterations
    for (int j = tid; j < NPTS; j += TPB) {
        float qx = p2[j*3+0], qy = p2[j*3+1], qz = p2[j*3+2];
        sj[j] = make_float4(qx, qy, qz, 0.5f*fmaf(qx,qx,fmaf(qy,qy,qz*qz)));
    }
    if (tid < IPC) {
        int i = cta*IPC + tid;
        float x = p1[i*3+0], y = p1[i*3+1], z = p1[i*3+2];
        myp1[tid*3+0] = x; myp1[tid*3+1] = y; myp1[tid*3+2] = z;
        mypc[tid*3+0] = x; mypc[tid*3+1] = y; mypc[tid*3+2] = z;
    }
    __syncthreads();

    const int iblk  = tid & 7;        // 8 i-blocks of 4 points
    const int slice = tid >> 3;       // 32 j-slices of 128
    const int ib4   = iblk*4;

    for (int k = 0; k <= STEPS; k++) {
        // apply R_{k-1}, t_{k-1}: pc_k = R pc_{k-1} + t
        if (k > 0 && tid < IPC) {
            float x = mypc[tid*3+0], y = mypc[tid*3+1], z = mypc[tid*3+2];
            float nx = fmaf(srt[0],x, fmaf(srt[1],y, fmaf(srt[2],z, srt[9])));
            float ny = fmaf(srt[3],x, fmaf(srt[4],y, fmaf(srt[5],z, srt[10])));
            float nz = fmaf(srt[6],x, fmaf(srt[7],y, fmaf(srt[8],z, srt[11])));
            mypc[tid*3+0] = nx; mypc[tid*3+1] = ny; mypc[tid*3+2] = nz;
        }
        __syncthreads();

        if (k < STEPS) {
            // --- NN: 4 i-points x 128 j per thread, score = |q|^2/2 - p.q ---
            float x0=mypc[(ib4+0)*3+0], y0=mypc[(ib4+0)*3+1], z0=mypc[(ib4+0)*3+2];
            float x1=mypc[(ib4+1)*3+0], y1=mypc[(ib4+1)*3+1], z1=mypc[(ib4+1)*3+2];
            float x2=mypc[(ib4+2)*3+0], y2=mypc[(ib4+2)*3+1], z2=mypc[(ib4+2)*3+2];
            float x3=mypc[(ib4+3)*3+0], y3=mypc[(ib4+3)*3+1], z3=mypc[(ib4+3)*3+2];

            float b0=3.4028235e38f, b1=b0, b2=b0, b3=b0;
            int   j0=0, j1=0, j2=0, j3=0;
            const int jbeg = slice*128;
            #pragma unroll 8
            for (int jj = jbeg; jj < jbeg + 128; jj++) {
                float4 q = sj[jj];
                float s0 = fmaf(-x0,q.x, fmaf(-y0,q.y, fmaf(-z0,q.z, q.w)));
                float s1 = fmaf(-x1,q.x, fmaf(-y1,q.y, fmaf(-z1,q.z, q.w)));
                float s2 = fmaf(-x2,q.x, fmaf(-y2,q.y, fmaf(-z2,q.z, q.w)));
                float s3 = fmaf(-x3,q.x, fmaf(-y3,q.y, fmaf(-z3,q.z, q.w)));
                if (s0 < b0) { b0 = s0; j0 = jj; }   // strict <: first index on ties
                if (s1 < b1) { b1 = s1; j1 = jj; }
                if (s2 < b2) { b2 = s2; j2 = jj; }
                if (s3 < b3) { b3 = s3; j3 = jj; }
            }
            key[slice*32 + ib4+0] = ((unsigned long long)fkey(b0) << 32) | (unsigned)j0;
            key[slice*32 + ib4+1] = ((unsigned long long)fkey(b1) << 32) | (unsigned)j1;
            key[slice*32 + ib4+2] = ((unsigned long long)fkey(b2) << 32) | (unsigned)j2;
            key[slice*32 + ib4+3] = ((unsigned long long)fkey(b3) << 32) | (unsigned)j3;
            __syncthreads();
        }

        // --- per-CTA covariance partials (warp 0) + global arrive ---
        if (tid < 32) {
            float sx, sy, sz, dx, dy, dz;
            if (k < STEPS) {
                unsigned long long best = key[tid];
                #pragma unroll 8
                for (int s2 = 1; s2 < 32; s2++) {
                    unsigned long long v = key[s2*32 + tid];
                    if (v < best) best = v;   // (score, j) lexicographic: first-index ties
                }
                const int idx = (int)(unsigned)(best & 0xFFFFFFFFu);
                float4 q = sj[idx];
                dx = q.x; dy = q.y; dz = q.z;
                sx = mypc[tid*3+0]; sy = mypc[tid*3+1]; sz = mypc[tid*3+2];
            } else {
                sx = myp1[tid*3+0]; sy = myp1[tid*3+1]; sz = myp1[tid*3+2];
                dx = mypc[tid*3+0]; dy = mypc[tid*3+1]; dz = mypc[tid*3+2];
            }
            float a[15];
            a[0]=sx; a[1]=sy; a[2]=sz; a[3]=dx; a[4]=dy; a[5]=dz;
            a[6]=sx*dx; a[7]=sx*dy; a[8]=sx*dz;
            a[9]=sy*dx; a[10]=sy*dy; a[11]=sy*dz;
            a[12]=sz*dx; a[13]=sz*dy; a[14]=sz*dz;
            wred15(a);
            if (tid == 0) {
                volatile float* gp = g_part[cta];
                #pragma unroll
                for (int q = 0; q < 15; q++) gp[q] = a[q];
                __threadfence();
                atomicAdd(&g_sync[k], 1);
            }
        }

        // --- every CTA: wait for all partials, reduce, solve locally ---
        if (tid == 0) {
            while (((volatile int*)g_sync)[k] < NCTA) __nanosleep(32);
        }
        __syncthreads();
        __threadfence();
        {
            float a[15];
            if (tid < NCTA) {
                volatile float* gp = g_part[tid];
                #pragma unroll
                for (int q = 0; q < 15; q++) a[q] = gp[q];
                wred15(a);
                if ((tid & 31) == 0) {
                    #pragma unroll
                    for (int q = 0; q < 15; q++) sred[(tid>>5)*15 + q] = a[q];
                }
            }
        }
        __syncthreads();
        if (tid == 0) {
            float s15[15];
            #pragma unroll
            for (int q = 0; q < 15; q++)
                s15[q] = (sred[q] + sred[15+q]) + (sred[30+q] + sred[45+q]);
            const float invN = 1.0f/NPTS;
            float c1[3] = { s15[0]*invN, s15[1]*invN, s15[2]*invN };
            float c2[3] = { s15[3]*invN, s15[4]*invN, s15[5]*invN };
            float R[9], t[3];
            kabsch3(&s15[6], (float)NPTS, c1, c2, R, t);
            if (k < STEPS) {
                #pragma unroll
                for (int q = 0; q < 9; q++) srt[q] = R[q];
                srt[9]=t[0]; srt[10]=t[1]; srt[11]=t[2];
            } else if (cta == 0) {
                #pragma unroll
                for (int r = 0; r < 3; r++) {
                    out[r*4+0]=R[r*3+0]; out[r*4+1]=R[r*3+1];
                    out[r*4+2]=R[r*3+2]; out[r*4+3]=t[r];
                }
            }
        }
        __syncthreads();
    }
}

extern "C" void kernel_launch(void* const* d_in, const int* in_sizes, int n_in,
                              void* d_out, int out_size)
{
    const float* p1 = (const float*)d_in[0];
    const float* p2 = (const float*)d_in[1];
    float* out = (float*)d_out;

    int* SYNC;
    cudaGetSymbolAddress((void**)&SYNC, g_sync);
    cudaMemsetAsync(SYNC, 0, 64*sizeof(int), 0);

    static int attr_set = 0;
    if (!attr_set) {
        cudaFuncSetAttribute(icp_all, cudaFuncAttributeMaxDynamicSharedMemorySize,
                             SM_TOTAL);
        attr_set = 1;
    }
    icp_all<<<NCTA, TPB, SM_TOTAL>>>(p1, p2, out);
}

// round 5
// speedup vs baseline: 1.1498x; 1.1498x over previous
#include <cuda_runtime.h>

#define NPTS  4096
#define NCTA  128
#define TPB   256
#define IPC   32          // i-points per CTA
#define STEPS 10

// shared memory layout (bytes)
#define SM_SJ    0                       // float4[4096]  = 65536
#define SM_KEY   (NPTS*16)               // u64[32][32]   = 8192
#define SM_MYPC  (SM_KEY + 32*32*8)      // float[96]
#define SM_MYP1  (SM_MYPC + 96*4)        // float[96]
#define SM_SRT   (SM_MYP1 + 96*4)        // float[12] (+pad)
#define SM_SRED  (SM_SRT + 16*4)         // float[4][15]
#define SM_TOTAL (SM_SRED + 4*15*4 + 64)

// global scratch (no allocations allowed)
__device__ float g_part[NCTA][16];
__device__ float g_rel[16];    // [0..11] R,t ; [15] release flag (int bits); one 64B line
__device__ int   g_sync[64];   // [0..STEPS] arrival counters

__device__ __forceinline__ unsigned int fkey(float f) {
    unsigned int u = __float_as_uint(f);
    return (u & 0x80000000u) ? ~u : (u | 0x80000000u);
}

// ---------------------------------------------------------------------------
// Fast float Kabsch from raw product sums P[r*3+c]=sum s_r d_c.
// H = P - n c1 c2^T ; R = V diag(1,1,det) U^T ; t = c2 - R c1.
// Fixed 5 Jacobi sweeps, fully unrolled, MUFU-based div/rsqrt.
// ---------------------------------------------------------------------------
__device__ __forceinline__ void kabsch3(const float* __restrict__ P, float n,
                                        const float c1[3], const float c2[3],
                                        float R[9], float t[3])
{
    float H[9];
    #pragma unroll
    for (int r = 0; r < 3; r++)
        #pragma unroll
        for (int c = 0; c < 3; c++)
            H[r*3+c] = P[r*3+c] - n*c1[r]*c2[c];

    float S[3][3], V[3][3];
    #pragma unroll
    for (int r = 0; r < 3; r++)
        #pragma unroll
        for (int c = 0; c < 3; c++) {
            S[r][c] = H[0+r]*H[0+c] + H[3+r]*H[3+c] + H[6+r]*H[6+c];
            V[r][c] = (r == c) ? 1.f : 0.f;
        }

    #pragma unroll
    for (int sweep = 0; sweep < 5; sweep++) {
        #pragma unroll
        for (int pair = 0; pair < 3; pair++) {
            const int p = (pair == 2) ? 1 : 0;
            const int q = (pair == 0) ? 1 : 2;
            float apq = S[p][q];
            if (fabsf(apq) > 1e-30f) {
                float theta = __fdividef(S[q][q] - S[p][p], 2.f*apq);
                float tj = __fdividef((theta >= 0.f) ? 1.f : -1.f,
                                      fabsf(theta) + sqrtf(fmaf(theta,theta,1.f)));
                float cj = rsqrtf(fmaf(tj,tj,1.f));
                float sj = tj*cj;
                #pragma unroll
                for (int k = 0; k < 3; k++) {
                    float skp = S[k][p], skq = S[k][q];
                    S[k][p] = cj*skp - sj*skq;
                    S[k][q] = sj*skp + cj*skq;
                }
                #pragma unroll
                for (int k = 0; k < 3; k++) {
                    float spk = S[p][k], sqk = S[q][k];
                    S[p][k] = cj*spk - sj*sqk;
                    S[q][k] = sj*spk + cj*sqk;
                }
                #pragma unroll
                for (int k = 0; k < 3; k++) {
                    float vkp = V[k][p], vkq = V[k][q];
                    V[k][p] = cj*vkp - sj*vkq;
                    V[k][q] = sj*vkp + cj*vkq;
                }
            }
        }
    }

    float lam[3] = { S[0][0], S[1][1], S[2][2] };
    int ord[3] = {0,1,2};
    #pragma unroll
    for (int a = 0; a < 2; a++)
        #pragma unroll
        for (int b = a+1; b < 3; b++)
            if (lam[ord[b]] > lam[ord[a]]) { int tmp = ord[a]; ord[a] = ord[b]; ord[b] = tmp; }
    float Vs[3][3];
    #pragma unroll
    for (int c = 0; c < 3; c++)
        #pragma unroll
        for (int r = 0; r < 3; r++) Vs[r][c] = V[r][ord[c]];

    float U[3][3];
    #pragma unroll
    for (int c = 0; c < 3; c++) {
        float u0 = H[0]*Vs[0][c] + H[1]*Vs[1][c] + H[2]*Vs[2][c];
        float u1 = H[3]*Vs[0][c] + H[4]*Vs[1][c] + H[5]*Vs[2][c];
        float u2 = H[6]*Vs[0][c] + H[7]*Vs[1][c] + H[8]*Vs[2][c];
        float n2 = fmaf(u0,u0, fmaf(u1,u1, u2*u2));
        if (n2 > 1e-30f) {
            float inv = rsqrtf(n2);
            u0 *= inv; u1 *= inv; u2 *= inv;
        } else if (c == 2) {   // rank-deficient fallback: u2 = u0 x u1
            u0 = U[1][0]*U[2][1] - U[2][0]*U[1][1];
            u1 = U[2][0]*U[0][1] - U[0][0]*U[2][1];
            u2 = U[0][0]*U[1][1] - U[1][0]*U[0][1];
        }
        U[0][c] = u0; U[1][c] = u1; U[2][c] = u2;
    }
    float detV = Vs[0][0]*(Vs[1][1]*Vs[2][2]-Vs[1][2]*Vs[2][1])
               - Vs[0][1]*(Vs[1][0]*Vs[2][2]-Vs[1][2]*Vs[2][0])
               + Vs[0][2]*(Vs[1][0]*Vs[2][1]-Vs[1][1]*Vs[2][0]);
    float detU = U[0][0]*(U[1][1]*U[2][2]-U[1][2]*U[2][1])
               - U[0][1]*(U[1][0]*U[2][2]-U[1][2]*U[2][0])
               + U[0][2]*(U[1][0]*U[2][1]-U[1][1]*U[2][0]);
    float d = (detV*detU < 0.f) ? -1.f : 1.f;

    #pragma unroll
    for (int r = 0; r < 3; r++)
        #pragma unroll
        for (int c = 0; c < 3; c++)
            R[r*3+c] = Vs[r][0]*U[c][0] + Vs[r][1]*U[c][1] + d*Vs[r][2]*U[c][2];
    #pragma unroll
    for (int r = 0; r < 3; r++)
        t[r] = c2[r] - (R[r*3+0]*c1[0] + R[r*3+1]*c1[1] + R[r*3+2]*c1[2]);
}

// warp-reduce 15 accumulators (full warp, fixed order -> deterministic)
__device__ __forceinline__ void wred15(float a[15]) {
    #pragma unroll
    for (int q = 0; q < 15; q++)
        #pragma unroll
        for (int off = 16; off; off >>= 1)
            a[q] += __shfl_down_sync(0xffffffffu, a[q], off);
}

// ---------------------------------------------------------------------------
// Persistent kernel: all STEPS iterations + final Kabsch. grid=NCTA, block=TPB.
// Sync topology: arrivals -> counter (read ONLY by CTA0); CTA0 solves and
// publishes R,t + iteration-tagged flag in one cache line (single writer,
// many nanosleep-backed readers).
// ---------------------------------------------------------------------------
__global__ void __launch_bounds__(TPB, 1)
icp_all(const float* __restrict__ p1, const float* __restrict__ p2,
        float* __restrict__ out)
{
    extern __shared__ unsigned char smem[];
    float4*             sj   = (float4*)(smem + SM_SJ);
    unsigned long long* key  = (unsigned long long*)(smem + SM_KEY);
    float*              mypc = (float*)(smem + SM_MYPC);
    float*              myp1 = (float*)(smem + SM_MYP1);
    float*              srt  = (float*)(smem + SM_SRT);
    float*              sred = (float*)(smem + SM_SRED);

    const int cta = blockIdx.x;
    const int tid = threadIdx.x;

    // load p2 (+ precomputed 0.5|q|^2) into shared; reused all iterations
    for (int j = tid; j < NPTS; j += TPB) {
        float qx = p2[j*3+0], qy = p2[j*3+1], qz = p2[j*3+2];
        sj[j] = make_float4(qx, qy, qz, 0.5f*fmaf(qx,qx,fmaf(qy,qy,qz*qz)));
    }
    if (tid < IPC) {
        int i = cta*IPC + tid;
        float x = p1[i*3+0], y = p1[i*3+1], z = p1[i*3+2];
        myp1[tid*3+0] = x; myp1[tid*3+1] = y; myp1[tid*3+2] = z;
        mypc[tid*3+0] = x; mypc[tid*3+1] = y; mypc[tid*3+2] = z;
    }
    __syncthreads();

    const int iblk  = tid & 7;        // 8 i-blocks of 4 points
    const int slice = tid >> 3;       // 32 j-slices of 128
    const int ib4   = iblk*4;

    for (int k = 0; k <= STEPS; k++) {
        // apply R_{k-1}, t_{k-1}: pc_k = R pc_{k-1} + t
        if (k > 0 && tid < IPC) {
            float x = mypc[tid*3+0], y = mypc[tid*3+1], z = mypc[tid*3+2];
            float nx = fmaf(srt[0],x, fmaf(srt[1],y, fmaf(srt[2],z, srt[9])));
            float ny = fmaf(srt[3],x, fmaf(srt[4],y, fmaf(srt[5],z, srt[10])));
            float nz = fmaf(srt[6],x, fmaf(srt[7],y, fmaf(srt[8],z, srt[11])));
            mypc[tid*3+0] = nx; mypc[tid*3+1] = ny; mypc[tid*3+2] = nz;
        }
        __syncthreads();

        if (k < STEPS) {
            // --- NN: 4 i-points x 128 j per thread, score = |q|^2/2 - p.q ---
            float x0=mypc[(ib4+0)*3+0], y0=mypc[(ib4+0)*3+1], z0=mypc[(ib4+0)*3+2];
            float x1=mypc[(ib4+1)*3+0], y1=mypc[(ib4+1)*3+1], z1=mypc[(ib4+1)*3+2];
            float x2=mypc[(ib4+2)*3+0], y2=mypc[(ib4+2)*3+1], z2=mypc[(ib4+2)*3+2];
            float x3=mypc[(ib4+3)*3+0], y3=mypc[(ib4+3)*3+1], z3=mypc[(ib4+3)*3+2];

            float b0=3.4028235e38f, b1=b0, b2=b0, b3=b0;
            int   j0=0, j1=0, j2=0, j3=0;
            const int jbeg = slice*128;
            #pragma unroll 8
            for (int jj = jbeg; jj < jbeg + 128; jj++) {
                float4 q = sj[jj];
                float s0 = fmaf(-x0,q.x, fmaf(-y0,q.y, fmaf(-z0,q.z, q.w)));
                float s1 = fmaf(-x1,q.x, fmaf(-y1,q.y, fmaf(-z1,q.z, q.w)));
                float s2 = fmaf(-x2,q.x, fmaf(-y2,q.y, fmaf(-z2,q.z, q.w)));
                float s3 = fmaf(-x3,q.x, fmaf(-y3,q.y, fmaf(-z3,q.z, q.w)));
                if (s0 < b0) { b0 = s0; j0 = jj; }   // strict <: first index on ties
                if (s1 < b1) { b1 = s1; j1 = jj; }
                if (s2 < b2) { b2 = s2; j2 = jj; }
                if (s3 < b3) { b3 = s3; j3 = jj; }
            }
            key[slice*32 + ib4+0] = ((unsigned long long)fkey(b0) << 32) | (unsigned)j0;
            key[slice*32 + ib4+1] = ((unsigned long long)fkey(b1) << 32) | (unsigned)j1;
            key[slice*32 + ib4+2] = ((unsigned long long)fkey(b2) << 32) | (unsigned)j2;
            key[slice*32 + ib4+3] = ((unsigned long long)fkey(b3) << 32) | (unsigned)j3;
            __syncthreads();
        }

        // --- per-CTA covariance partials (warp 0) + arrive ---
        if (tid < 32) {
            float sx, sy, sz, dx, dy, dz;
            if (k < STEPS) {
                unsigned long long best = key[tid];
                #pragma unroll 8
                for (int s2 = 1; s2 < 32; s2++) {
                    unsigned long long v = key[s2*32 + tid];
                    if (v < best) best = v;   // (score, j) lexicographic: first-index ties
                }
                const int idx = (int)(unsigned)(best & 0xFFFFFFFFu);
                float4 q = sj[idx];
                dx = q.x; dy = q.y; dz = q.z;
                sx = mypc[tid*3+0]; sy = mypc[tid*3+1]; sz = mypc[tid*3+2];
            } else {
                sx = myp1[tid*3+0]; sy = myp1[tid*3+1]; sz = myp1[tid*3+2];
                dx = mypc[tid*3+0]; dy = mypc[tid*3+1]; dz = mypc[tid*3+2];
            }
            float a[15];
            a[0]=sx; a[1]=sy; a[2]=sz; a[3]=dx; a[4]=dy; a[5]=dz;
            a[6]=sx*dx; a[7]=sx*dy; a[8]=sx*dz;
            a[9]=sy*dx; a[10]=sy*dy; a[11]=sy*dz;
            a[12]=sz*dx; a[13]=sz*dy; a[14]=sz*dz;
            wred15(a);
            if (tid == 0) {
                volatile float* gp = g_part[cta];
                #pragma unroll
                for (int q = 0; q < 15; q++) gp[q] = a[q];
                __threadfence();
                atomicAdd(&g_sync[k], 1);
            }
        }

        if (cta == 0) {
            // --- CTA0: wait (sole reader of counter), reduce, solve, publish ---
            if (tid == 0) {
                while (((volatile int*)g_sync)[k] < NCTA) { /* busy poll */ }
            }
            __syncthreads();
            __threadfence();
            {
                float a[15];
                if (tid < NCTA) {
                    volatile float* gp = g_part[tid];
                    #pragma unroll
                    for (int q = 0; q < 15; q++) a[q] = gp[q];
                    wred15(a);
                    if ((tid & 31) == 0) {
                        #pragma unroll
                        for (int q = 0; q < 15; q++) sred[(tid>>5)*15 + q] = a[q];
                    }
                }
            }
            __syncthreads();
            if (tid == 0) {
                float s15[15];
                #pragma unroll
                for (int q = 0; q < 15; q++)
                    s15[q] = (sred[q] + sred[15+q]) + (sred[30+q] + sred[45+q]);
                const float invN = 1.0f/NPTS;
                float c1[3] = { s15[0]*invN, s15[1]*invN, s15[2]*invN };
                float c2[3] = { s15[3]*invN, s15[4]*invN, s15[5]*invN };
                float R[9], t[3];
                kabsch3(&s15[6], (float)NPTS, c1, c2, R, t);
                if (k < STEPS) {
                    #pragma unroll
                    for (int q = 0; q < 9; q++) { srt[q] = R[q]; ((volatile float*)g_rel)[q] = R[q]; }
                    srt[9]=t[0];  ((volatile float*)g_rel)[9]  = t[0];
                    srt[10]=t[1]; ((volatile float*)g_rel)[10] = t[1];
                    srt[11]=t[2]; ((volatile float*)g_rel)[11] = t[2];
                    __threadfence();
                    ((volatile int*)g_rel)[15] = k + 1;   // release (same line as data)
                } else {
                    #pragma unroll
                    for (int r = 0; r < 3; r++) {
                        out[r*4+0]=R[r*3+0]; out[r*4+1]=R[r*3+1];
                        out[r*4+2]=R[r*3+2]; out[r*4+3]=t[r];
                    }
                }
            }
            __syncthreads();
        } else if (k < STEPS) {
            // --- other CTAs: wait for release, pick up R,t (one line) ---
            if (tid == 0) {
                while (((volatile int*)g_rel)[15] < k + 1) __nanosleep(64);
            }
            __syncthreads();
            __threadfence();
            if (tid < 12) srt[tid] = ((volatile float*)g_rel)[tid];
            __syncthreads();
        }
    }
}

extern "C" void kernel_launch(void* const* d_in, const int* in_sizes, int n_in,
                              void* d_out, int out_size)
{
    const float* p1 = (const float*)d_in[0];
    const float* p2 = (const float*)d_in[1];
    float* out = (float*)d_out;

    int* SYNC;
    float* REL;
    cudaGetSymbolAddress((void**)&SYNC, g_sync);
    cudaGetSymbolAddress((void**)&REL,  g_rel);
    cudaMemsetAsync(SYNC, 0, 64*sizeof(int), 0);
    cudaMemsetAsync(REL,  0, 16*sizeof(float), 0);

    static int attr_set = 0;
    if (!attr_set) {
        cudaFuncSetAttribute(icp_all, cudaFuncAttributeMaxDynamicSharedMemorySize,
                             SM_TOTAL);
        attr_set = 1;
    }
    icp_all<<<NCTA, TPB, SM_TOTAL>>>(p1, p2, out);
}